// round 4
// baseline (speedup 1.0000x reference)
#include <cuda_runtime.h>

#define TT 1024
#define HH 128
#define BPC 2          // batches per CTA
#define NTHREADS 256

__device__ __forceinline__ unsigned long long ffma2(unsigned long long a,
                                                    unsigned long long b,
                                                    unsigned long long c) {
    unsigned long long d;
    asm("fma.rn.f32x2 %0, %1, %2, %3;" : "=l"(d) : "l"(a), "l"(b), "l"(c));
    return d;
}

__device__ __forceinline__ float2 unpack_f32x2(unsigned long long v) {
    float2 f;
    asm("mov.b64 {%0, %1}, %2;" : "=f"(f.x), "=f"(f.y) : "l"(v));
    return f;
}

__global__ __launch_bounds__(NTHREADS, 1)
void rnn_m2m_kernel(const float* __restrict__ x,      // [B, T, 1]
                    const float* __restrict__ W_ih,   // [H, 1]
                    const float* __restrict__ W_hh,   // [H, H]
                    const float* __restrict__ b_ih,   // [H]
                    const float* __restrict__ b_hh,   // [H]
                    const float* __restrict__ W_fc,   // [2, H]
                    const float* __restrict__ b_fc,   // [2]
                    float* __restrict__ out)          // [B, T, 2]
{
    __shared__ __align__(16) float xs[BPC][TT];        // 8 KB: input preload
    __shared__ __align__(16) float hs[2][BPC][HH];     // 2 KB: double-buffered h
    __shared__ float parts[2][BPC][4][2];              // logit partials, double-buffered

    const int tid  = threadIdx.x;
    const int bl   = tid >> 7;        // batch-local 0/1
    const int h    = tid & (HH - 1);
    const int b    = blockIdx.x * BPC + bl;
    const int lane = h & 31;
    const int wb   = h >> 5;          // warp index within batch (0..3)

    // ---- preload W_hh row h into 64 packed f32x2 registers ----
    unsigned long long w[HH / 2];
    {
        const ulonglong2* wrow = (const ulonglong2*)(W_hh + h * HH);
        #pragma unroll
        for (int j = 0; j < HH / 4; j++) {
            ulonglong2 v = wrow[j];
            w[2 * j]     = v.x;
            w[2 * j + 1] = v.y;
        }
    }
    const float wih  = W_ih[h];
    const float bias = b_ih[h] + b_hh[h];
    const float wf0  = W_fc[h];
    const float wf1  = W_fc[HH + h];
    const float bfc  = (h == 0) ? b_fc[0] : b_fc[1];   // only used by h<2

    // ---- preload x for both batches of this CTA ----
    {
        const int b0 = blockIdx.x * BPC;
        for (int i = tid; i < BPC * TT; i += NTHREADS) {
            int bb = i >> 10;            // T = 1024
            int t0 = i & (TT - 1);
            xs[bb][t0] = x[(b0 + bb) * TT + t0];
        }
    }

    hs[0][bl][h] = 0.0f;
    __syncthreads();

    for (int t = 0; t < TT; t++) {
        const int cur = t & 1;
        const int nxt = cur ^ 1;

        // ---- 128-wide dot: h_old · W_hh[h,:] via packed f32x2 FMA ----
        unsigned long long a0 = 0ull, a1 = 0ull, a2 = 0ull, a3 = 0ull;
        const ulonglong2* hv = (const ulonglong2*)&hs[cur][bl][0];
        #pragma unroll
        for (int j = 0; j < HH / 4; j += 2) {
            ulonglong2 p = hv[j];
            a0 = ffma2(p.x, w[2 * j],     a0);
            a1 = ffma2(p.y, w[2 * j + 1], a1);
            ulonglong2 q = hv[j + 1];
            a2 = ffma2(q.x, w[2 * j + 2], a2);
            a3 = ffma2(q.y, w[2 * j + 3], a3);
        }
        float2 f0 = unpack_f32x2(a0);
        float2 f1 = unpack_f32x2(a1);
        float2 f2 = unpack_f32x2(a2);
        float2 f3 = unpack_f32x2(a3);
        float dot = ((f0.x + f0.y) + (f1.x + f1.y)) +
                    ((f2.x + f2.y) + (f3.x + f3.y));

        float pre = fmaf(xs[bl][t], wih, dot + bias);

        // tanh(x) = 1 - 2/(exp(2x)+1)   (MUFU EX2 + RCP path, ~1e-6 rel err)
        float e  = __expf(pre + pre);
        float hn = 1.0f - __fdividef(2.0f, e + 1.0f);

        hs[nxt][bl][h] = hn;

        // ---- fused logits: per-warp butterfly reduce of hn*W_fc ----
        float p0 = hn * wf0;
        float p1 = hn * wf1;
        #pragma unroll
        for (int o = 16; o > 0; o >>= 1) {
            p0 += __shfl_xor_sync(0xffffffffu, p0, o);
            p1 += __shfl_xor_sync(0xffffffffu, p1, o);
        }
        if (lane == 0) {
            parts[nxt][bl][wb][0] = p0;
            parts[nxt][bl][wb][1] = p1;
        }

        __syncthreads();   // publishes hs[nxt] and parts[nxt]

        if (h < 2) {
            float s = parts[nxt][bl][0][h] + parts[nxt][bl][1][h] +
                      parts[nxt][bl][2][h] + parts[nxt][bl][3][h] + bfc;
            out[(b * TT + t) * 2 + h] = s;
        }
    }
}

extern "C" void kernel_launch(void* const* d_in, const int* in_sizes, int n_in,
                              void* d_out, int out_size) {
    const float* x    = (const float*)d_in[0];
    const float* W_ih = (const float*)d_in[1];
    const float* W_hh = (const float*)d_in[2];
    const float* b_ih = (const float*)d_in[3];
    const float* b_hh = (const float*)d_in[4];
    const float* W_fc = (const float*)d_in[5];
    const float* b_fc = (const float*)d_in[6];
    float* out = (float*)d_out;

    rnn_m2m_kernel<<<256 / BPC, NTHREADS>>>(x, W_ih, W_hh, b_ih, b_hh, W_fc, b_fc, out);
}

// round 9
// speedup vs baseline: 1.2954x; 1.2954x over previous
#include <cuda_runtime.h>

#define TT 1024
#define HH 128
#define BB 256
#define BPC 2          // batches per CTA
#define NTHREADS 256
#define K2_THREADS 256

// 256*1024*128 floats = 128 MB scratch for the hidden-state sequence [B,T,H]
__device__ float g_hseq[(size_t)BB * TT * HH];

__device__ __forceinline__ unsigned long long ffma2(unsigned long long a,
                                                    unsigned long long b,
                                                    unsigned long long c) {
    unsigned long long d;
    asm("fma.rn.f32x2 %0, %1, %2, %3;" : "=l"(d) : "l"(a), "l"(b), "l"(c));
    return d;
}

__device__ __forceinline__ unsigned long long addf2(unsigned long long a,
                                                    unsigned long long b) {
    unsigned long long d;
    asm("add.rn.f32x2 %0, %1, %2;" : "=l"(d) : "l"(a), "l"(b));
    return d;
}

__device__ __forceinline__ unsigned long long pack2(float lo, float hi) {
    unsigned long long d;
    asm("mov.b64 %0, {%1, %2};" : "=l"(d) : "f"(lo), "f"(hi));
    return d;
}

__device__ __forceinline__ float2 unpack_f32x2(unsigned long long v) {
    float2 f;
    asm("mov.b64 {%0, %1}, %2;" : "=f"(f.x), "=f"(f.y) : "l"(v));
    return f;
}

// ---------------------------------------------------------------------------
// Kernel 1: the serial recurrence. h_t = tanh(xp_t + h_{t-1} @ W_hh^T)
// One CTA = 2 batch rows; thread (bl, h) owns hidden unit h of row bl.
// The two rows never synchronize with each other (named barriers).
// ---------------------------------------------------------------------------
__global__ __launch_bounds__(NTHREADS, 1)
void rnn_rec_kernel(const float* __restrict__ x,      // [B, T, 1]
                    const float* __restrict__ W_ih,   // [H, 1]
                    const float* __restrict__ W_hh,   // [H, H]
                    const float* __restrict__ b_ih,   // [H]
                    const float* __restrict__ b_hh)   // [H]
{
    __shared__ __align__(16) float xs[BPC][TT];        // 8 KB input preload
    __shared__ __align__(16) float hs[2][BPC][HH];     // double-buffered h

    const int tid = threadIdx.x;
    const int bl  = tid >> 7;         // batch-local 0/1
    const int h   = tid & (HH - 1);
    const int b   = blockIdx.x * BPC + bl;
    const int bar = bl + 1;           // named barrier id for this row's 4 warps

    // ---- W_hh row h -> 64 packed f32x2 registers ----
    unsigned long long w[HH / 2];
    {
        const ulonglong2* wrow = (const ulonglong2*)(W_hh + h * HH);
        #pragma unroll
        for (int j = 0; j < HH / 4; j++) {
            ulonglong2 v = wrow[j];
            w[2 * j]     = v.x;
            w[2 * j + 1] = v.y;
        }
    }
    const float wih  = W_ih[h];
    const float bias = b_ih[h] + b_hh[h];

    // ---- preload x for this row only (group-local, covered by named barrier) ----
    for (int i = h; i < TT; i += HH)
        xs[bl][i] = x[b * TT + i];

    hs[0][bl][h] = 0.0f;
    asm volatile("bar.sync %0, 128;" :: "r"(bar) : "memory");

    float* hout = g_hseq + (size_t)b * TT * HH + h;

    for (int t = 0; t < TT; t++) {
        const int cur = t & 1;
        const int nxt = cur ^ 1;

        // 128-wide dot via packed f32x2 FMA; bias folded into a0 init.
        unsigned long long a0 = pack2(bias, 0.0f);
        unsigned long long a1 = 0ull, a2 = 0ull, a3 = 0ull;
        const ulonglong2* hv = (const ulonglong2*)&hs[cur][bl][0];
        #pragma unroll
        for (int j = 0; j < HH / 4; j += 2) {
            ulonglong2 p = hv[j];
            a0 = ffma2(p.x, w[2 * j],     a0);
            a1 = ffma2(p.y, w[2 * j + 1], a1);
            ulonglong2 q = hv[j + 1];
            a2 = ffma2(q.x, w[2 * j + 2], a2);
            a3 = ffma2(q.y, w[2 * j + 3], a3);
        }
        unsigned long long s = addf2(addf2(a0, a1), addf2(a2, a3));
        float2 f = unpack_f32x2(s);
        float pre = fmaf(xs[bl][t], wih, f.x + f.y);

        // tanh(x) = 1 - 2/(exp(2x)+1)   (EX2 + RCP, ~1e-6 rel err)
        float e  = __expf(pre + pre);
        float hn = 1.0f - __fdividef(2.0f, e + 1.0f);

        hs[nxt][bl][h] = hn;
        hout[(size_t)t * HH] = hn;     // coalesced 128B per warp

        asm volatile("bar.sync %0, 128;" :: "r"(bar) : "memory");
    }
}

// ---------------------------------------------------------------------------
// Kernel 2: streaming logits. out[b,t,c] = sum_h hseq[b,t,h]*W_fc[c,h] + b_fc[c]
// One thread per (b,t) row; memory-bound.
// ---------------------------------------------------------------------------
__global__ __launch_bounds__(K2_THREADS)
void rnn_fc_kernel(const float* __restrict__ W_fc,   // [2, H]
                   const float* __restrict__ b_fc,   // [2]
                   float* __restrict__ out)          // [B, T, 2]
{
    __shared__ __align__(16) float wf[2][HH];
    __shared__ float bf[2];

    const int tid = threadIdx.x;
    if (tid < HH) {
        wf[0][tid] = W_fc[tid];
        wf[1][tid] = W_fc[HH + tid];
    }
    if (tid < 2) bf[tid] = b_fc[tid];
    __syncthreads();

    const size_t r = (size_t)blockIdx.x * K2_THREADS + tid;   // row in [0, B*T)
    const float4* hv = (const float4*)(g_hseq + r * HH);
    const float4* w0 = (const float4*)wf[0];
    const float4* w1 = (const float4*)wf[1];

    float acc0 = 0.0f, acc1 = 0.0f;
    #pragma unroll
    for (int j = 0; j < HH / 4; j++) {
        float4 v  = hv[j];
        float4 a  = w0[j];
        float4 c  = w1[j];
        acc0 = fmaf(v.x, a.x, acc0); acc0 = fmaf(v.y, a.y, acc0);
        acc0 = fmaf(v.z, a.z, acc0); acc0 = fmaf(v.w, a.w, acc0);
        acc1 = fmaf(v.x, c.x, acc1); acc1 = fmaf(v.y, c.y, acc1);
        acc1 = fmaf(v.z, c.z, acc1); acc1 = fmaf(v.w, c.w, acc1);
    }
    float2 res = make_float2(acc0 + bf[0], acc1 + bf[1]);
    ((float2*)out)[r] = res;           // coalesced 8B/thread
}

extern "C" void kernel_launch(void* const* d_in, const int* in_sizes, int n_in,
                              void* d_out, int out_size) {
    const float* x    = (const float*)d_in[0];
    const float* W_ih = (const float*)d_in[1];
    const float* W_hh = (const float*)d_in[2];
    const float* b_ih = (const float*)d_in[3];
    const float* b_hh = (const float*)d_in[4];
    const float* W_fc = (const float*)d_in[5];
    const float* b_fc = (const float*)d_in[6];
    float* out = (float*)d_out;

    rnn_rec_kernel<<<BB / BPC, NTHREADS>>>(x, W_ih, W_hh, b_ih, b_hh);
    rnn_fc_kernel<<<(BB * TT) / K2_THREADS, K2_THREADS>>>(W_fc, b_fc, out);
}